// round 16
// baseline (speedup 1.0000x reference)
#include <cuda_runtime.h>
#include <cstdint>

#define NT 512
constexpr int Tn  = 16;
constexpr int Bn  = 16;
constexpr int Nn  = 1024;
constexpr int En  = 16384;
constexpr int Fin = 128;
constexpr int Hn  = 256;
constexpr int Kn  = 820;
constexpr int NG  = Tn * Bn;   // 256 graphs

// ---------------- global scratch ----------------
__device__ float          g_emb[NG * Hn];
__device__ float          g_ihpre[NG * 4 * Hn];
__device__ float          g_h[2 * Bn * Hn];
__device__ unsigned       g_cnt[Bn * Tn];
__device__ float          g_A[(size_t)NG * Nn * 16];     // 16 MB node-feature scratch
__device__ unsigned short g_srcs[(size_t)NG * En];       // 8 MB CSR sources

__device__ __forceinline__ float sigmoidf_(float v) { return 1.0f / (1.0f + expf(-v)); }

// ---------------- f32x2 helpers ----------------
__device__ __forceinline__ unsigned long long pk2(float a, float b) {
    unsigned long long r; asm("mov.b64 %0,{%1,%2};" : "=l"(r) : "f"(a), "f"(b)); return r;
}
__device__ __forceinline__ float2 upk(unsigned long long v) {
    float2 o; asm("mov.b64 {%0,%1},%2;" : "=f"(o.x), "=f"(o.y) : "l"(v)); return o;
}
__device__ __forceinline__ unsigned long long ffma2(unsigned long long a, unsigned long long b, unsigned long long c) {
    unsigned long long d; asm("fma.rn.f32x2 %0,%1,%2,%3;" : "=l"(d) : "l"(a), "l"(b), "l"(c)); return d;
}
__device__ __forceinline__ float hsum2(unsigned long long v) { float2 o = upk(v); return o.x + o.y; }

// score <-> ascending-sortable-key (key = ~u so small key = large score)
__device__ __forceinline__ unsigned score_key(float s) {
    unsigned u = __float_as_uint(s);
    u = (u & 0x80000000u) ? ~u : (u | 0x80000000u);
    return ~u;
}
__device__ __forceinline__ float key_score(unsigned key) {
    const unsigned u = ~key;
    const unsigned orig = (u & 0x80000000u) ? (u & 0x7FFFFFFFu) : ~u;
    return __uint_as_float(orig);
}

// conv1 half (f32x2): 256 threads (gt in [0,256)), nodes [pb, pb+512)
__device__ __forceinline__ void conv1_half(const float* __restrict__ xg,
                                           const unsigned long long* w1p,
                                           float* __restrict__ A, int gt, int pb)
{
    const int mq = gt & 3;
    const int nb = gt >> 2;
    const int c0 = mq * 4;
    for (int n = pb + nb; n < pb + 512; n += 64) {
        unsigned long long a0 = 0, a1 = 0, a2 = 0, a3 = 0;
        const ulonglong2* xr = (const ulonglong2*)(xg + (size_t)n * Fin);
        #pragma unroll 8
        for (int i = 0; i < 32; i++) {
            const ulonglong2 xv = xr[i];
            const ulonglong2* wp = (const ulonglong2*)&w1p[(2 * i) * 16 + c0];
            const ulonglong2* wq = (const ulonglong2*)&w1p[(2 * i + 1) * 16 + c0];
            const ulonglong2 wa = wp[0], wb = wp[1];
            const ulonglong2 wc = wq[0], wd = wq[1];
            a0 = ffma2(xv.x, wa.x, a0); a1 = ffma2(xv.x, wa.y, a1);
            a2 = ffma2(xv.x, wb.x, a2); a3 = ffma2(xv.x, wb.y, a3);
            a0 = ffma2(xv.y, wc.x, a0); a1 = ffma2(xv.y, wc.y, a1);
            a2 = ffma2(xv.y, wd.x, a2); a3 = ffma2(xv.y, wd.y, a3);
        }
        *(float4*)&A[n * 16 + c0] = make_float4(hsum2(a0), hsum2(a1), hsum2(a2), hsum2(a3));
    }
}

// =====================================================================
// K1: per-graph embedding. One CTA (512 thr). smem 111888 B, regs<=64 so
// TWO independent CTAs co-reside per SM (overlap LSU vs FMA phases).
// A + srcs live in global (L1/L2-cached); arithmetic identical to R15.
// =====================================================================
__global__ __launch_bounds__(NT, 2) void k_embed(
    const float* __restrict__ x, const int* __restrict__ ei,
    const float* __restrict__ W1, const float* __restrict__ b1,
    const float* __restrict__ Wl, const float* __restrict__ Wr,
    const float* __restrict__ sb,
    const float* __restrict__ W2, const float* __restrict__ b2)
{
    extern __shared__ float sm[];
    float*              Bf     = sm;                                  // 16384
    unsigned*           keysu  = (unsigned*)(sm + 16384);             // 1024 (later redf)
    int*                off    = (int*)(sm + 17408);                  // 1028
    int*                cur    = (int*)(sm + 18436);                  // 1024 (later tvf)
    float*              pv     = sm + 19460;                          // 1024 (dinv,p,bins,dinv2)
    int*                newidx = (int*)(sm + 20484);                  // 1024 (first scoretmp)
    unsigned long long* w1p    = (unsigned long long*)(sm + 21508);   // 1024 u64
    float*              w2s    = sm + 23556;                          // 4096 (aliases tmppos)
    unsigned char*      tmppos = (unsigned char*)(sm + 23556);        // 16384 u8
    float*              b2s    = sm + 27652;                          // 256
    float*              cst    = sm + 27908;                          // 64
    // total 27972 floats = 111888 B

    const int tid = threadIdx.x;
    const int g   = blockIdx.x;
    const float* xg   = x  + (size_t)g * Nn * Fin;
    const int*   srcp = ei + (size_t)g * 2 * En;
    const int*   dstp = srcp + En;
    float*          A    = g_A    + (size_t)g * Nn * 16;
    unsigned short* srcs = g_srcs + (size_t)g * En;

    for (int i = tid; i < 1024; i += NT) {
        const int f2 = i >> 4, c = i & 15;
        w1p[i] = pk2(W1[(2 * f2) * 16 + c], W1[(2 * f2 + 1) * 16 + c]);
    }
    if (tid < 16) { cst[tid] = b1[tid]; cst[16 + tid] = Wl[tid]; cst[32 + tid] = Wr[tid]; }
    if (tid == 0) cst[48] = sb[0];
    for (int i = tid; i < Nn; i += NT) cur[i] = 0;
    if (g == 0 && tid < Bn * Tn) g_cnt[tid] = 0u;
    __syncthreads();

    // --- phase A: warps 0-7 conv1 nodes [0,512) || warps 8-15 histogram+rank
    if (tid < 256) {
        conv1_half(xg, w1p, A, tid, 0);
    } else {
        for (int e = tid - 256; e < En; e += 256)
            tmppos[e] = (unsigned char)atomicAdd(&cur[dstp[e]], 1);
    }
    __syncthreads();

    // --- exclusive Blelloch scan of counts -> off[0..1024] ------------------
    for (int i = tid; i < Nn; i += NT) off[i] = cur[i];
    for (int d2 = 1; d2 < Nn; d2 <<= 1) {
        __syncthreads();
        const int idx = (tid + 1) * (d2 << 1) - 1;
        if (idx < Nn) off[idx] += off[idx - d2];
    }
    __syncthreads();
    if (tid == 0) { off[Nn] = off[Nn - 1]; off[Nn - 1] = 0; }
    for (int d2 = Nn >> 1; d2 >= 1; d2 >>= 1) {
        __syncthreads();
        const int idx = (tid + 1) * (d2 << 1) - 1;
        if (idx < Nn) { const int t = off[idx - d2]; off[idx - d2] = off[idx]; off[idx] += t; }
    }
    __syncthreads();
    for (int i = tid; i < Nn; i += NT)
        pv[i] = rsqrtf(1.0f + (float)(off[i + 1] - off[i]));   // dinv
    __syncthreads();

    // --- phase C: warps 0-7 conv1 nodes [512,1024) || warps 8-15 placement --
    if (tid < 256) {
        conv1_half(xg, w1p, A, tid, 512);
    } else {
        for (int e = tid - 256; e < En; e += 256)
            srcs[off[dstp[e]] + tmppos[e]] = (unsigned short)srcp[e];
    }
    __syncthreads();

    // tmppos dead -> load W2/b2 into its alias; pre-scale A rows by dinv
    for (int i = tid; i < 16 * Hn; i += NT) w2s[i] = W2[i];
    for (int i = tid; i < Hn; i += NT) b2s[i] = b2[i];
    for (int i = tid; i < Nn * 16; i += NT) A[i] *= pv[i >> 4];
    __syncthreads();

    // --- conv1 gather (pure sum, self included) + bias + relu -> Bf = h1 ----
    {
        const int grp = tid >> 2, q = tid & 3;
        const float bx = cst[q * 4 + 0], by = cst[q * 4 + 1];
        const float bz = cst[q * 4 + 2], bw = cst[q * 4 + 3];
        for (int d = grp; d < Nn; d += 128) {
            const int e0 = off[d], e1 = off[d + 1];
            float4 ac = *(const float4*)&A[d * 16 + q * 4];
            for (int j = e0; j < e1; j++) {
                const float4 v = *(const float4*)&A[(int)srcs[j] * 16 + q * 4];
                ac.x += v.x; ac.y += v.y; ac.z += v.z; ac.w += v.w;
            }
            const float dd = pv[d];
            float4 o;
            o.x = fmaxf(fmaf(ac.x, dd, bx), 0.f);
            o.y = fmaxf(fmaf(ac.y, dd, by), 0.f);
            o.z = fmaxf(fmaf(ac.z, dd, bz), 0.f);
            o.w = fmaxf(fmaf(ac.w, dd, bw), 0.f);
            *(float4*)&Bf[d * 16 + q * 4] = o;
        }
    }
    __syncthreads();

    // --- p[n] = h1[n].Wl -> pv ; partial score -> scoretmp (newidx alias) ---
    {
        float* scoretmp = (float*)newidx;
        for (int n = tid; n < Nn; n += NT) {
            float pl = 0.f, pr = cst[48];
            #pragma unroll
            for (int m = 0; m < 16; m++) {
                const float h = Bf[n * 16 + m];
                pl = fmaf(h, cst[16 + m], pl);
                pr = fmaf(h, cst[32 + m], pr);
            }
            pv[n] = pl; scoretmp[n] = pr;
        }
    }
    __syncthreads();

    // --- full score -> 32-bit sortable key ------------------------------------
    {
        const float* scoretmp = (const float*)newidx;
        for (int d = tid; d < Nn; d += NT) {
            float s = scoretmp[d];
            const int e0 = off[d], e1 = off[d + 1];
            for (int j = e0; j < e1; j++) s += pv[(int)srcs[j]];
            keysu[d] = score_key(s);
        }
    }
    __syncthreads();

    // --- radix-select: exact Kn-th smallest u32 key ----------------------------
    unsigned thr;
    {
        unsigned* bins = (unsigned*)pv;                 // pv dead (dinv/p done)
        unsigned* selp = (unsigned*)(pv + 256);
        unsigned* kkp  = (unsigned*)(pv + 257);
        if (tid == 0) { *selp = 0u; *kkp = (unsigned)Kn; }
        for (int p = 3; p >= 0; p--) {
            const int sh = p * 8;
            __syncthreads();
            for (int i = tid; i < 256; i += NT) bins[i] = 0u;
            __syncthreads();
            const unsigned pref = *selp;
            for (int n = tid; n < Nn; n += NT) {
                const unsigned key = keysu[n];
                const bool match = (p == 3) || ((key >> (sh + 8)) == (pref >> (sh + 8)));
                if (match) atomicAdd(&bins[(key >> sh) & 255u], 1u);
            }
            __syncthreads();
            if (tid < 32) {
                unsigned c[8], s = 0;
                #pragma unroll
                for (int i = 0; i < 8; i++) { c[i] = bins[tid * 8 + i]; s += c[i]; }
                unsigned incl = s;
                #pragma unroll
                for (int o = 1; o < 32; o <<= 1) {
                    const unsigned v = __shfl_up_sync(0xFFFFFFFFu, incl, o);
                    if (tid >= o) incl += v;
                }
                const unsigned excl = incl - s;
                const unsigned kk = *kkp;
                if (kk > excl && kk <= incl) {
                    unsigned run = excl;
                    #pragma unroll
                    for (int i = 0; i < 8; i++) {
                        if (kk > run && kk <= run + c[i]) {
                            *selp = pref | ((unsigned)(tid * 8 + i) << sh);
                            *kkp  = kk - run;
                            break;
                        }
                        run += c[i];
                    }
                }
            }
        }
        __syncthreads();
        thr = *selp;
    }
    __syncthreads();

    // --- compaction: newidx[n] = rank among kept, else -1 ----------------------
    for (int n = tid; n < Nn; n += NT)
        newidx[n] = (keysu[n] <= thr) ? 1 : 0;
    for (int d2 = 1; d2 < Nn; d2 <<= 1) {
        __syncthreads();
        const int idx = (tid + 1) * (d2 << 1) - 1;
        if (idx < Nn) newidx[idx] += newidx[idx - d2];
    }
    __syncthreads();
    if (tid == 0) newidx[Nn - 1] = 0;
    for (int d2 = Nn >> 1; d2 >= 1; d2 >>= 1) {
        __syncthreads();
        const int idx = (tid + 1) * (d2 << 1) - 1;
        if (idx < Nn) { const int t = newidx[idx - d2]; newidx[idx - d2] = newidx[idx]; newidx[idx] += t; }
    }
    __syncthreads();
    {
        float* tvf = (float*)cur;
        for (int n = tid; n < Nn; n += NT) {
            if (keysu[n] <= thr) tvf[newidx[n]] = tanhf(key_score(keysu[n]));
            else                 newidx[n] = -1;
        }
    }
    __syncthreads();

    // --- gated xp scatter: A rows [0,Kn) ---------------------------------------
    {
        const float* tvf = (const float*)cur;
        for (int i = tid; i < Nn * 16; i += NT) {
            const int n = i >> 4, m = i & 15;
            const int r = newidx[n];
            if (r >= 0) A[r * 16 + m] = Bf[i] * tvf[r];
        }
    }
    __syncthreads();

    // --- deg2 over valid remapped edges (dinv2 aliases pv) ----------------------
    float* dinv2 = pv;
    for (int d = tid; d < Nn; d += NT) {
        const int nd = newidx[d];
        if (nd >= 0) {
            int c = 0;
            const int e0 = off[d], e1 = off[d + 1];
            for (int j = e0; j < e1; j++) c += (newidx[(int)srcs[j]] >= 0);
            dinv2[nd] = rsqrtf(1.0f + (float)c);
        }
    }
    __syncthreads();
    for (int i = tid; i < Kn * 16; i += NT) A[i] *= dinv2[i >> 4];   // pre-scale xp
    __syncthreads();

    // --- conv2 pre-aggregation (MID space) -> Bf rows [0,Kn) ---------------------
    {
        const int grp = tid >> 2, q = tid & 3;
        for (int d = grp; d < Nn; d += 128) {
            const int nd = newidx[d];
            if (nd < 0) continue;
            const int e0 = off[d], e1 = off[d + 1];
            float4 ac = *(const float4*)&A[nd * 16 + q * 4];
            for (int j = e0; j < e1; j++) {
                const int ns = newidx[(int)srcs[j]];
                if (ns >= 0) {
                    const float4 v = *(const float4*)&A[ns * 16 + q * 4];
                    ac.x += v.x; ac.y += v.y; ac.z += v.z; ac.w += v.w;
                }
            }
            const float dd = dinv2[nd];
            *(float4*)&Bf[nd * 16 + q * 4] = make_float4(ac.x * dd, ac.y * dd, ac.z * dd, ac.w * dd);
        }
    }
    __syncthreads();

    // --- h2 = relu(pre @ W2 + b2), mean over K -> g_emb --------------------------
    // thread: 2 channels (c0 = (tid&127)*2), rows rq::4 (rq = tid>>7). 16 u64 wregs.
    {
        const int c0 = (tid & 127) * 2, rq = tid >> 7;
        unsigned long long wreg[16];
        #pragma unroll
        for (int i = 0; i < 2; i++)
            #pragma unroll
            for (int k2 = 0; k2 < 8; k2++)
                wreg[i * 8 + k2] = pk2(w2s[(2 * k2) * Hn + c0 + i], w2s[(2 * k2 + 1) * Hn + c0 + i]);
        float accs[2] = {0.f, 0.f};
        const float bias0 = b2s[c0], bias1 = b2s[c0 + 1];

        for (int r = rq; r < Kn; r += 4) {
            const ulonglong2* pr = (const ulonglong2*)&Bf[r * 16];
            const ulonglong2 v0 = pr[0], v1 = pr[1], v2 = pr[2], v3 = pr[3];
            #pragma unroll
            for (int i = 0; i < 2; i++) {
                unsigned long long dd_ = 0;
                dd_ = ffma2(v0.x, wreg[i * 8 + 0], dd_);
                dd_ = ffma2(v0.y, wreg[i * 8 + 1], dd_);
                dd_ = ffma2(v1.x, wreg[i * 8 + 2], dd_);
                dd_ = ffma2(v1.y, wreg[i * 8 + 3], dd_);
                dd_ = ffma2(v2.x, wreg[i * 8 + 4], dd_);
                dd_ = ffma2(v2.y, wreg[i * 8 + 5], dd_);
                dd_ = ffma2(v3.x, wreg[i * 8 + 6], dd_);
                dd_ = ffma2(v3.y, wreg[i * 8 + 7], dd_);
                accs[i] += fmaxf(hsum2(dd_) + (i ? bias1 : bias0), 0.f);
            }
        }
        float* redf = (float*)keysu;   // keys dead (1024 floats = 4 x 256)
        redf[rq * 256 + c0]     = accs[0];
        redf[rq * 256 + c0 + 1] = accs[1];
        __syncthreads();
        if (tid < 256) {
            const float s = redf[tid] + redf[256 + tid] + redf[512 + tid] + redf[768 + tid];
            g_emb[(size_t)g * Hn + tid] = s * (1.0f / (float)Kn);
        }
    }
}

// =====================================================================
// K2: ihpre (verified R11 kernel)
// =====================================================================
__global__ __launch_bounds__(256) void k_prep(
    const float* __restrict__ W_ih, const float* __restrict__ b_ih,
    const float* __restrict__ b_hh)
{
    __shared__ float wih[16 * 260];
    __shared__ float embt[16 * 260];
    __shared__ float bs[16];
    const int tid = threadIdx.x;
    const int j0  = blockIdx.x * 16;

    for (int idx = tid; idx < 16 * 256; idx += 256)
        wih[(idx >> 8) * 260 + (idx & 255)] = W_ih[(size_t)(j0 + (idx >> 8)) * Hn + (idx & 255)];
    if (tid < 16) bs[tid] = b_ih[j0 + tid] + b_hh[j0 + tid];
    __syncthreads();

    const int rl = tid & 15, gl = tid >> 4;
    for (int tile = 0; tile < 16; tile++) {
        const int gb = tile * 16;
        for (int idx = tid; idx < 16 * 256; idx += 256)
            embt[(idx >> 8) * 260 + (idx & 255)] = g_emb[(size_t)(gb + (idx >> 8)) * Hn + (idx & 255)];
        __syncthreads();
        unsigned long long acc = 0;
        const ulonglong2* ev = (const ulonglong2*)&embt[gl * 260];
        const ulonglong2* wv = (const ulonglong2*)&wih[rl * 260];
        #pragma unroll 8
        for (int k4 = 0; k4 < 64; k4++) {
            const ulonglong2 e = ev[k4], w = wv[k4];
            acc = ffma2(e.x, w.x, acc);
            acc = ffma2(e.y, w.y, acc);
        }
        g_ihpre[(size_t)(gb + gl) * 1024 + j0 + rl] = hsum2(acc) + bs[rl];
        __syncthreads();
    }
}

// =====================================================================
// K3: LSTM recurrence (verified R11 kernel)
// =====================================================================
__global__ __launch_bounds__(512) void k_lstm(
    const float* __restrict__ W_hh, const float* __restrict__ cls_W,
    const float* __restrict__ cls_b, float* __restrict__ out)
{
    __shared__ float hsb[2 * 288];
    __shared__ float iht[Tn * 32 * 4];
    __shared__ float wbuf[32 * 264];
    const int tid  = threadIdx.x;
    const int b    = blockIdx.x >> 3;
    const int rank = blockIdx.x & 7;
    const int kc = tid & 7;
    const int jp = tid >> 3;
    const int q0 = 2 * jp, q1 = 2 * jp + 1;

    for (int idx = tid; idx < Tn * 32 * 4; idx += 512) {
        const int t = idx >> 7, gate = (idx >> 5) & 3, hu = idx & 31;
        iht[(t * 32 + hu) * 4 + gate] =
            g_ihpre[(size_t)(t * Bn + b) * 1024 + gate * 256 + rank * 32 + hu];
    }
    for (int i = tid; i < 288; i += 512) hsb[i] = 0.f;

    unsigned long long wA[16], wB[16];
    #pragma unroll
    for (int gblk = 0; gblk < 4; gblk++) {
        __syncthreads();
        const float* src = W_hh + (size_t)(gblk * 256 + rank * 32) * Hn;
        for (int idx = tid; idx < 2048; idx += 512) {
            const int r = idx >> 6, c4 = idx & 63;
            *(float4*)&wbuf[r * 264 + c4 * 4] = __ldg((const float4*)&src[r * 256 + c4 * 4]);
        }
        __syncthreads();
        if ((q0 & 3) == gblk) {
            const int m = q0 >> 2;
            #pragma unroll
            for (int i = 0; i < 16; i++)
                wA[i] = pk2(wbuf[m * 264 + kc * 32 + 2 * i], wbuf[m * 264 + kc * 32 + 2 * i + 1]);
        }
        if ((q1 & 3) == gblk) {
            const int m = q1 >> 2;
            #pragma unroll
            for (int i = 0; i < 16; i++)
                wB[i] = pk2(wbuf[m * 264 + kc * 32 + 2 * i], wbuf[m * 264 + kc * 32 + 2 * i + 1]);
        }
    }
    __syncthreads();

    const int lane = tid & 31;
    const int warp = tid >> 5;
    const bool epi = ((lane & 15) == 0);
    const int  ehu = 2 * warp + (lane >> 4);
    float creg = 0.f;

    for (int t = 0; t < Tn; t++) {
        const ulonglong2* hv = (const ulonglong2*)&hsb[(t & 1) * 288 + kc * 36];
        unsigned long long aA = 0, aB = 0;
        #pragma unroll
        for (int i2 = 0; i2 < 8; i2++) {
            const ulonglong2 h2 = hv[i2];
            aA = ffma2(h2.x, wA[2 * i2],     aA);
            aA = ffma2(h2.y, wA[2 * i2 + 1], aA);
            aB = ffma2(h2.x, wB[2 * i2],     aB);
            aB = ffma2(h2.y, wB[2 * i2 + 1], aB);
        }
        float fA = hsum2(aA), fB = hsum2(aB);
        fA += __shfl_xor_sync(0xFFFFFFFFu, fA, 1);
        fA += __shfl_xor_sync(0xFFFFFFFFu, fA, 2);
        fA += __shfl_xor_sync(0xFFFFFFFFu, fA, 4);
        fB += __shfl_xor_sync(0xFFFFFFFFu, fB, 1);
        fB += __shfl_xor_sync(0xFFFFFFFFu, fB, 2);
        fB += __shfl_xor_sync(0xFFFFFFFFu, fB, 4);

        const int base = lane & 16;
        const float gi = __shfl_sync(0xFFFFFFFFu, fA, base);
        const float gf = __shfl_sync(0xFFFFFFFFu, fB, base);
        const float gg = __shfl_sync(0xFFFFFFFFu, fA, base + 8);
        const float go = __shfl_sync(0xFFFFFFFFu, fB, base + 8);

        if (epi) {
            const float4 ihv = *(const float4*)&iht[(t * 32 + ehu) * 4];
            creg = sigmoidf_(gf + ihv.y) * creg + sigmoidf_(gi + ihv.x) * tanhf(gg + ihv.z);
            const float hn = sigmoidf_(go + ihv.w) * tanhf(creg);
            __stcg(&g_h[((t + 1) & 1) * (Bn * Hn) + b * Hn + rank * 32 + ehu], hn);
        }
        __syncthreads();

        if (tid == 0)
            asm volatile("red.release.gpu.global.add.u32 [%0], %1;"
                         :: "l"(&g_cnt[b * Tn + t]), "r"(1u) : "memory");
        if (tid < 64) {
            unsigned v;
            do {
                asm volatile("ld.global.acquire.gpu.u32 %0,[%1];"
                             : "=r"(v) : "l"(&g_cnt[b * Tn + t]));
            } while (v < 8u);
            if (t < Tn - 1) {
                const float4 hvv = __ldcg((const float4*)
                    &g_h[((t + 1) & 1) * (Bn * Hn) + b * Hn + tid * 4]);
                *(float4*)&hsb[((t + 1) & 1) * 288 + (tid >> 3) * 36 + (tid & 7) * 4] = hvv;
            }
        }
        __syncthreads();
    }

    if (rank == 0 && tid < 32) {
        float p = 0.f;
        #pragma unroll
        for (int i = 0; i < 8; i++)
            p += __ldcg(&g_h[0 * (Bn * Hn) + b * Hn + i * 32 + tid])
                 * __ldg(&cls_W[i * 32 + tid]);
        #pragma unroll
        for (int o = 16; o; o >>= 1) p += __shfl_xor_sync(0xFFFFFFFFu, p, o);
        if (tid == 0) out[b] = p + cls_b[0];
    }
}

// =====================================================================
extern "C" void kernel_launch(void* const* d_in, const int* in_sizes, int n_in,
                              void* d_out, int out_size)
{
    (void)in_sizes; (void)n_in; (void)out_size;
    const float* x     = (const float*)d_in[0];
    const int*   ei    = (const int*)  d_in[1];
    const float* W1    = (const float*)d_in[2];
    const float* b1    = (const float*)d_in[3];
    const float* Wl    = (const float*)d_in[4];
    const float* Wr    = (const float*)d_in[5];
    const float* sb    = (const float*)d_in[6];
    const float* W2    = (const float*)d_in[7];
    const float* b2    = (const float*)d_in[8];
    const float* W_ih  = (const float*)d_in[9];
    const float* W_hh  = (const float*)d_in[10];
    const float* b_ih  = (const float*)d_in[11];
    const float* b_hh  = (const float*)d_in[12];
    const float* cls_W = (const float*)d_in[13];
    const float* cls_b = (const float*)d_in[14];
    float* out = (float*)d_out;

    const size_t smem1 = 27972 * sizeof(float);  // 111888 B (2 CTAs/SM)
    cudaFuncSetAttribute(k_embed, cudaFuncAttributeMaxDynamicSharedMemorySize, (int)smem1);

    k_embed<<<NG, NT, smem1>>>(x, ei, W1, b1, Wl, Wr, sb, W2, b2);
    k_prep <<<64, 256>>>(W_ih, b_ih, b_hh);
    k_lstm <<<128, 512>>>(W_hh, cls_W, cls_b, out);
}

// round 17
// speedup vs baseline: 1.0937x; 1.0937x over previous
#include <cuda_runtime.h>
#include <cstdint>

#define NT 512
constexpr int Tn  = 16;
constexpr int Bn  = 16;
constexpr int Nn  = 1024;
constexpr int En  = 16384;
constexpr int Fin = 128;
constexpr int Hn  = 256;
constexpr int Kn  = 820;
constexpr int NG  = Tn * Bn;   // 256 graphs

// ---------------- global scratch ----------------
__device__ float    g_emb[NG * Hn];
__device__ float    g_ihpre[NG * 4 * Hn];  // [g][j], j = gate*256 + hu (bias folded)
__device__ float    g_h[2 * Bn * Hn];      // double-buffered hidden state
__device__ unsigned g_cnt[Bn * Tn];        // per-batch per-step arrival counters

__device__ __forceinline__ float sigmoidf_(float v) { return 1.0f / (1.0f + expf(-v)); }

// ---------------- f32x2 helpers ----------------
__device__ __forceinline__ unsigned long long pk2(float a, float b) {
    unsigned long long r; asm("mov.b64 %0,{%1,%2};" : "=l"(r) : "f"(a), "f"(b)); return r;
}
__device__ __forceinline__ float2 upk(unsigned long long v) {
    float2 o; asm("mov.b64 {%0,%1},%2;" : "=f"(o.x), "=f"(o.y) : "l"(v)); return o;
}
__device__ __forceinline__ unsigned long long ffma2(unsigned long long a, unsigned long long b, unsigned long long c) {
    unsigned long long d; asm("fma.rn.f32x2 %0,%1,%2,%3;" : "=l"(d) : "l"(a), "l"(b), "l"(c)); return d;
}
__device__ __forceinline__ float hsum2(unsigned long long v) { float2 o = upk(v); return o.x + o.y; }

// score -> ascending-sortable u32 key (small key = large score; exact)
__device__ __forceinline__ unsigned score_key(float s) {
    unsigned u = __float_as_uint(s);
    u = (u & 0x80000000u) ? ~u : (u | 0x80000000u);
    return ~u;
}

// conv1 half (f32x2): 256 threads (gt in [0,256)), nodes [pb, pb+512)
__device__ __forceinline__ void conv1_half(const float* __restrict__ xg,
                                           const unsigned long long* w1p,
                                           float* A, int gt, int pb)
{
    const int mq = gt & 3;
    const int nb = gt >> 2;
    const int c0 = mq * 4;
    for (int n = pb + nb; n < pb + 512; n += 64) {
        unsigned long long a0 = 0, a1 = 0, a2 = 0, a3 = 0;
        const ulonglong2* xr = (const ulonglong2*)(xg + (size_t)n * Fin);
        #pragma unroll 8
        for (int i = 0; i < 32; i++) {
            const ulonglong2 xv = xr[i];
            const ulonglong2* wp = (const ulonglong2*)&w1p[(2 * i) * 16 + c0];
            const ulonglong2* wq = (const ulonglong2*)&w1p[(2 * i + 1) * 16 + c0];
            const ulonglong2 wa = wp[0], wb = wp[1];
            const ulonglong2 wc = wq[0], wd = wq[1];
            a0 = ffma2(xv.x, wa.x, a0); a1 = ffma2(xv.x, wa.y, a1);
            a2 = ffma2(xv.x, wb.x, a2); a3 = ffma2(xv.x, wb.y, a3);
            a0 = ffma2(xv.y, wc.x, a0); a1 = ffma2(xv.y, wc.y, a1);
            a2 = ffma2(xv.y, wd.x, a2); a3 = ffma2(xv.y, wd.y, a3);
        }
        *(float4*)&A[n * 16 + c0] = make_float4(hsum2(a0), hsum2(a1), hsum2(a2), hsum2(a3));
    }
}

// =====================================================================
// K1: per-graph embedding. One CTA (512 thr) per graph.
// R15-verified body; radix-select now on 32-bit score keys (4 passes).
// =====================================================================
__global__ __launch_bounds__(NT) void k_embed(
    const float* __restrict__ x, const int* __restrict__ ei,
    const float* __restrict__ W1, const float* __restrict__ b1,
    const float* __restrict__ Wl, const float* __restrict__ Wr,
    const float* __restrict__ sb,
    const float* __restrict__ W2, const float* __restrict__ b2)
{
    extern __shared__ float sm[];
    float*              A      = sm;                                 // [0,16384)
    float*              Bf     = sm + 16384;                         // [16384,32768)
    unsigned*           keysu  = (unsigned*)(sm + 32768);            // 1024 u32 (region 2048 fl, later redf)
    unsigned short*     srcs   = (unsigned short*)(sm + 34816);      // 16384 u16
    int*                off    = (int*)(sm + 43008);                 // 1028
    int*                cur    = (int*)(sm + 44036);                 // 1024 (later tvf)
    float*              pv     = sm + 45060;                         // 1024 (dinv, p, then bins)
    float*              score  = sm + 46084;                         // 1024
    int*                newidx = (int*)(sm + 47108);                 // 1024
    float*              dinv2  = sm + 48132;                         // 1024
    unsigned long long* w1p    = (unsigned long long*)(sm + 49156);  // 1024 u64
    float*              w2s    = sm + 51204;                         // 4096 (aliases tmppos)
    unsigned char*      tmppos = (unsigned char*)(sm + 51204);       // 16384 u8
    float*              b2s    = sm + 55300;                         // 256
    float*              cst    = sm + 55556;                         // 64
    // total 55620 floats = 222480 B

    const int tid = threadIdx.x;
    const int g   = blockIdx.x;
    const float* xg   = x  + (size_t)g * Nn * Fin;
    const int*   srcp = ei + (size_t)g * 2 * En;
    const int*   dstp = srcp + En;

    for (int i = tid; i < 1024; i += NT) {
        const int f2 = i >> 4, c = i & 15;
        w1p[i] = pk2(W1[(2 * f2) * 16 + c], W1[(2 * f2 + 1) * 16 + c]);
    }
    if (tid < 16) { cst[tid] = b1[tid]; cst[16 + tid] = Wl[tid]; cst[32 + tid] = Wr[tid]; }
    if (tid == 0) cst[48] = sb[0];
    for (int i = tid; i < Nn; i += NT) cur[i] = 0;
    if (g == 0 && tid < Bn * Tn) g_cnt[tid] = 0u;
    __syncthreads();

    // --- phase A: warps 0-7 conv1 nodes [0,512) || warps 8-15 histogram+rank
    if (tid < 256) {
        conv1_half(xg, w1p, A, tid, 0);
    } else {
        for (int e = tid - 256; e < En; e += 256)
            tmppos[e] = (unsigned char)atomicAdd(&cur[dstp[e]], 1);
    }
    __syncthreads();

    // --- exclusive Blelloch scan of counts -> off[0..1024] ------------------
    for (int i = tid; i < Nn; i += NT) off[i] = cur[i];
    for (int d2 = 1; d2 < Nn; d2 <<= 1) {
        __syncthreads();
        const int idx = (tid + 1) * (d2 << 1) - 1;
        if (idx < Nn) off[idx] += off[idx - d2];
    }
    __syncthreads();
    if (tid == 0) { off[Nn] = off[Nn - 1]; off[Nn - 1] = 0; }
    for (int d2 = Nn >> 1; d2 >= 1; d2 >>= 1) {
        __syncthreads();
        const int idx = (tid + 1) * (d2 << 1) - 1;
        if (idx < Nn) { const int t = off[idx - d2]; off[idx - d2] = off[idx]; off[idx] += t; }
    }
    __syncthreads();
    for (int i = tid; i < Nn; i += NT)
        pv[i] = rsqrtf(1.0f + (float)(off[i + 1] - off[i]));   // dinv
    __syncthreads();

    // --- phase C: warps 0-7 conv1 nodes [512,1024) || warps 8-15 placement --
    if (tid < 256) {
        conv1_half(xg, w1p, A, tid, 512);
    } else {
        for (int e = tid - 256; e < En; e += 256)
            srcs[off[dstp[e]] + tmppos[e]] = (unsigned short)srcp[e];
    }
    __syncthreads();

    // tmppos dead -> load W2/b2 into its alias; pre-scale A rows by dinv
    for (int i = tid; i < 16 * Hn; i += NT) w2s[i] = W2[i];
    for (int i = tid; i < Hn; i += NT) b2s[i] = b2[i];
    for (int i = tid; i < Nn * 16; i += NT) A[i] *= pv[i >> 4];
    __syncthreads();

    // --- conv1 gather (pure sum, self included) + bias + relu -> Bf = h1 ----
    {
        const int grp = tid >> 2, q = tid & 3;
        const float bx = cst[q * 4 + 0], by = cst[q * 4 + 1];
        const float bz = cst[q * 4 + 2], bw = cst[q * 4 + 3];
        for (int d = grp; d < Nn; d += 128) {
            const int e0 = off[d], e1 = off[d + 1];
            float4 ac = *(const float4*)&A[d * 16 + q * 4];
            for (int j = e0; j < e1; j++) {
                const float4 v = *(const float4*)&A[srcs[j] * 16 + q * 4];
                ac.x += v.x; ac.y += v.y; ac.z += v.z; ac.w += v.w;
            }
            const float dd = pv[d];
            float4 o;
            o.x = fmaxf(fmaf(ac.x, dd, bx), 0.f);
            o.y = fmaxf(fmaf(ac.y, dd, by), 0.f);
            o.z = fmaxf(fmaf(ac.z, dd, bz), 0.f);
            o.w = fmaxf(fmaf(ac.w, dd, bw), 0.f);
            *(float4*)&Bf[d * 16 + q * 4] = o;
        }
    }
    __syncthreads();

    // --- p[n] = h1[n].Wl ; score[n] = h1[n].Wr + sag_b ----------------------
    for (int n = tid; n < Nn; n += NT) {
        float pl = 0.f, pr = cst[48];
        #pragma unroll
        for (int m = 0; m < 16; m++) {
            const float h = Bf[n * 16 + m];
            pl = fmaf(h, cst[16 + m], pl);
            pr = fmaf(h, cst[32 + m], pr);
        }
        pv[n] = pl; score[n] = pr;
    }
    __syncthreads();

    // --- score[d] += sum p[srcs] ; 32-bit sortable keys ------------------------
    for (int d = tid; d < Nn; d += NT) {
        float s = score[d];
        const int e0 = off[d], e1 = off[d + 1];
        for (int j = e0; j < e1; j++) s += pv[srcs[j]];
        score[d] = s;
        keysu[d] = score_key(s);
    }
    __syncthreads();

    // --- radix-select: exact Kn-th smallest u32 key (4 passes) -----------------
    unsigned thr;
    {
        unsigned* bins = (unsigned*)pv;                 // pv dead
        unsigned* selp = (unsigned*)(pv + 256);
        unsigned* kkp  = (unsigned*)(pv + 257);
        if (tid == 0) { *selp = 0u; *kkp = (unsigned)Kn; }
        for (int p = 3; p >= 0; p--) {
            const int sh = p * 8;
            __syncthreads();
            for (int i = tid; i < 256; i += NT) bins[i] = 0u;
            __syncthreads();
            const unsigned pref = *selp;
            for (int n = tid; n < Nn; n += NT) {
                const unsigned key = keysu[n];
                const bool match = (p == 3) || ((key >> (sh + 8)) == (pref >> (sh + 8)));
                if (match) atomicAdd(&bins[(key >> sh) & 255u], 1u);
            }
            __syncthreads();
            if (tid < 32) {
                unsigned c[8], s = 0;
                #pragma unroll
                for (int i = 0; i < 8; i++) { c[i] = bins[tid * 8 + i]; s += c[i]; }
                unsigned incl = s;
                #pragma unroll
                for (int o = 1; o < 32; o <<= 1) {
                    const unsigned v = __shfl_up_sync(0xFFFFFFFFu, incl, o);
                    if (tid >= o) incl += v;
                }
                const unsigned excl = incl - s;
                const unsigned kk = *kkp;
                if (kk > excl && kk <= incl) {
                    unsigned run = excl;
                    #pragma unroll
                    for (int i = 0; i < 8; i++) {
                        if (kk > run && kk <= run + c[i]) {
                            *selp = pref | ((unsigned)(tid * 8 + i) << sh);
                            *kkp  = kk - run;
                            break;
                        }
                        run += c[i];
                    }
                }
            }
        }
        __syncthreads();
        thr = *selp;
    }
    __syncthreads();

    // --- compaction: newidx[n] = rank among kept (order-free), else -1 ---------
    for (int n = tid; n < Nn; n += NT)
        newidx[n] = (keysu[n] <= thr) ? 1 : 0;
    for (int d2 = 1; d2 < Nn; d2 <<= 1) {
        __syncthreads();
        const int idx = (tid + 1) * (d2 << 1) - 1;
        if (idx < Nn) newidx[idx] += newidx[idx - d2];
    }
    __syncthreads();
    if (tid == 0) newidx[Nn - 1] = 0;
    for (int d2 = Nn >> 1; d2 >= 1; d2 >>= 1) {
        __syncthreads();
        const int idx = (tid + 1) * (d2 << 1) - 1;
        if (idx < Nn) { const int t = newidx[idx - d2]; newidx[idx - d2] = newidx[idx]; newidx[idx] += t; }
    }
    __syncthreads();
    {
        float* tvf = (float*)cur;
        for (int n = tid; n < Nn; n += NT) {
            if (keysu[n] <= thr) tvf[newidx[n]] = tanhf(score[n]);
            else                 newidx[n] = -1;
        }
    }
    __syncthreads();

    // --- gated xp scatter: A rows [0,Kn) ----------------------------------------
    {
        const float* tvf = (const float*)cur;
        for (int i = tid; i < Nn * 16; i += NT) {
            const int n = i >> 4, m = i & 15;
            const int r = newidx[n];
            if (r >= 0) A[r * 16 + m] = Bf[i] * tvf[r];
        }
    }
    __syncthreads();

    // --- deg2 over valid remapped edges -----------------------------------------
    for (int d = tid; d < Nn; d += NT) {
        const int nd = newidx[d];
        if (nd >= 0) {
            int c = 0;
            const int e0 = off[d], e1 = off[d + 1];
            for (int j = e0; j < e1; j++) c += (newidx[srcs[j]] >= 0);
            dinv2[nd] = rsqrtf(1.0f + (float)c);
        }
    }
    __syncthreads();
    for (int i = tid; i < Kn * 16; i += NT) A[i] *= dinv2[i >> 4];   // pre-scale xp
    __syncthreads();

    // --- conv2 pre-aggregation (MID space) -> Bf rows [0,Kn) ---------------------
    {
        const int grp = tid >> 2, q = tid & 3;
        for (int d = grp; d < Nn; d += 128) {
            const int nd = newidx[d];
            if (nd < 0) continue;
            const int e0 = off[d], e1 = off[d + 1];
            float4 ac = *(const float4*)&A[nd * 16 + q * 4];
            for (int j = e0; j < e1; j++) {
                const int ns = newidx[srcs[j]];
                if (ns >= 0) {
                    const float4 v = *(const float4*)&A[ns * 16 + q * 4];
                    ac.x += v.x; ac.y += v.y; ac.z += v.z; ac.w += v.w;
                }
            }
            const float dd = dinv2[nd];
            *(float4*)&Bf[nd * 16 + q * 4] = make_float4(ac.x * dd, ac.y * dd, ac.z * dd, ac.w * dd);
        }
    }
    __syncthreads();

    // --- h2 = relu(pre @ W2 + b2), mean over K -> g_emb (f32x2, regs) ------------
    {
        const int cg = tid & 63, rb = tid >> 6;
        const int c0 = cg * 4;
        unsigned long long wreg[32];
        #pragma unroll
        for (int i = 0; i < 4; i++)
            #pragma unroll
            for (int k2 = 0; k2 < 8; k2++)
                wreg[i * 8 + k2] = pk2(w2s[(2 * k2) * Hn + c0 + i], w2s[(2 * k2 + 1) * Hn + c0 + i]);
        float biasv[4], accs[4];
        #pragma unroll
        for (int i = 0; i < 4; i++) { biasv[i] = b2s[c0 + i]; accs[i] = 0.f; }

        for (int r = rb; r < Kn; r += 8) {
            const ulonglong2* pr = (const ulonglong2*)&Bf[r * 16];
            const ulonglong2 v0 = pr[0], v1 = pr[1], v2 = pr[2], v3 = pr[3];
            #pragma unroll
            for (int i = 0; i < 4; i++) {
                unsigned long long dd_ = 0;
                dd_ = ffma2(v0.x, wreg[i * 8 + 0], dd_);
                dd_ = ffma2(v0.y, wreg[i * 8 + 1], dd_);
                dd_ = ffma2(v1.x, wreg[i * 8 + 2], dd_);
                dd_ = ffma2(v1.y, wreg[i * 8 + 3], dd_);
                dd_ = ffma2(v2.x, wreg[i * 8 + 4], dd_);
                dd_ = ffma2(v2.y, wreg[i * 8 + 5], dd_);
                dd_ = ffma2(v3.x, wreg[i * 8 + 6], dd_);
                dd_ = ffma2(v3.y, wreg[i * 8 + 7], dd_);
                accs[i] += fmaxf(hsum2(dd_) + biasv[i], 0.f);
            }
        }
        float* redf = (float*)keysu;   // keys dead (region holds 2048 floats)
        #pragma unroll
        for (int i = 0; i < 4; i++) redf[rb * 256 + c0 + i] = accs[i];
        __syncthreads();
        if (tid < 256) {
            float s = 0.f;
            #pragma unroll
            for (int rbi = 0; rbi < 8; rbi++) s += redf[rbi * 256 + tid];
            g_emb[(size_t)g * Hn + tid] = s * (1.0f / (float)Kn);
        }
    }
}

// =====================================================================
// K2: ihpre (verified R11 kernel)
// =====================================================================
__global__ __launch_bounds__(256) void k_prep(
    const float* __restrict__ W_ih, const float* __restrict__ b_ih,
    const float* __restrict__ b_hh)
{
    __shared__ float wih[16 * 260];
    __shared__ float embt[16 * 260];
    __shared__ float bs[16];
    const int tid = threadIdx.x;
    const int j0  = blockIdx.x * 16;

    for (int idx = tid; idx < 16 * 256; idx += 256)
        wih[(idx >> 8) * 260 + (idx & 255)] = W_ih[(size_t)(j0 + (idx >> 8)) * Hn + (idx & 255)];
    if (tid < 16) bs[tid] = b_ih[j0 + tid] + b_hh[j0 + tid];
    __syncthreads();

    const int rl = tid & 15, gl = tid >> 4;
    for (int tile = 0; tile < 16; tile++) {
        const int gb = tile * 16;
        for (int idx = tid; idx < 16 * 256; idx += 256)
            embt[(idx >> 8) * 260 + (idx & 255)] = g_emb[(size_t)(gb + (idx >> 8)) * Hn + (idx & 255)];
        __syncthreads();
        unsigned long long acc = 0;
        const ulonglong2* ev = (const ulonglong2*)&embt[gl * 260];
        const ulonglong2* wv = (const ulonglong2*)&wih[rl * 260];
        #pragma unroll 8
        for (int k4 = 0; k4 < 64; k4++) {
            const ulonglong2 e = ev[k4], w = wv[k4];
            acc = ffma2(e.x, w.x, acc);
            acc = ffma2(e.y, w.y, acc);
        }
        g_ihpre[(size_t)(gb + gl) * 1024 + j0 + rl] = hsum2(acc) + bs[rl];
        __syncthreads();
    }
}

// =====================================================================
// K3: LSTM recurrence (verified R11 kernel)
// =====================================================================
__global__ __launch_bounds__(512) void k_lstm(
    const float* __restrict__ W_hh, const float* __restrict__ cls_W,
    const float* __restrict__ cls_b, float* __restrict__ out)
{
    __shared__ float hsb[2 * 288];
    __shared__ float iht[Tn * 32 * 4];
    __shared__ float wbuf[32 * 264];
    const int tid  = threadIdx.x;
    const int b    = blockIdx.x >> 3;
    const int rank = blockIdx.x & 7;
    const int kc = tid & 7;
    const int jp = tid >> 3;
    const int q0 = 2 * jp, q1 = 2 * jp + 1;

    for (int idx = tid; idx < Tn * 32 * 4; idx += 512) {
        const int t = idx >> 7, gate = (idx >> 5) & 3, hu = idx & 31;
        iht[(t * 32 + hu) * 4 + gate] =
            g_ihpre[(size_t)(t * Bn + b) * 1024 + gate * 256 + rank * 32 + hu];
    }
    for (int i = tid; i < 288; i += 512) hsb[i] = 0.f;

    unsigned long long wA[16], wB[16];
    #pragma unroll
    for (int gblk = 0; gblk < 4; gblk++) {
        __syncthreads();
        const float* src = W_hh + (size_t)(gblk * 256 + rank * 32) * Hn;
        for (int idx = tid; idx < 2048; idx += 512) {
            const int r = idx >> 6, c4 = idx & 63;
            *(float4*)&wbuf[r * 264 + c4 * 4] = __ldg((const float4*)&src[r * 256 + c4 * 4]);
        }
        __syncthreads();
        if ((q0 & 3) == gblk) {
            const int m = q0 >> 2;
            #pragma unroll
            for (int i = 0; i < 16; i++)
                wA[i] = pk2(wbuf[m * 264 + kc * 32 + 2 * i], wbuf[m * 264 + kc * 32 + 2 * i + 1]);
        }
        if ((q1 & 3) == gblk) {
            const int m = q1 >> 2;
            #pragma unroll
            for (int i = 0; i < 16; i++)
                wB[i] = pk2(wbuf[m * 264 + kc * 32 + 2 * i], wbuf[m * 264 + kc * 32 + 2 * i + 1]);
        }
    }
    __syncthreads();

    const int lane = tid & 31;
    const int warp = tid >> 5;
    const bool epi = ((lane & 15) == 0);
    const int  ehu = 2 * warp + (lane >> 4);
    float creg = 0.f;

    for (int t = 0; t < Tn; t++) {
        const ulonglong2* hv = (const ulonglong2*)&hsb[(t & 1) * 288 + kc * 36];
        unsigned long long aA = 0, aB = 0;
        #pragma unroll
        for (int i2 = 0; i2 < 8; i2++) {
            const ulonglong2 h2 = hv[i2];
            aA = ffma2(h2.x, wA[2 * i2],     aA);
            aA = ffma2(h2.y, wA[2 * i2 + 1], aA);
            aB = ffma2(h2.x, wB[2 * i2],     aB);
            aB = ffma2(h2.y, wB[2 * i2 + 1], aB);
        }
        float fA = hsum2(aA), fB = hsum2(aB);
        fA += __shfl_xor_sync(0xFFFFFFFFu, fA, 1);
        fA += __shfl_xor_sync(0xFFFFFFFFu, fA, 2);
        fA += __shfl_xor_sync(0xFFFFFFFFu, fA, 4);
        fB += __shfl_xor_sync(0xFFFFFFFFu, fB, 1);
        fB += __shfl_xor_sync(0xFFFFFFFFu, fB, 2);
        fB += __shfl_xor_sync(0xFFFFFFFFu, fB, 4);

        const int base = lane & 16;
        const float gi = __shfl_sync(0xFFFFFFFFu, fA, base);
        const float gf = __shfl_sync(0xFFFFFFFFu, fB, base);
        const float gg = __shfl_sync(0xFFFFFFFFu, fA, base + 8);
        const float go = __shfl_sync(0xFFFFFFFFu, fB, base + 8);

        if (epi) {
            const float4 ihv = *(const float4*)&iht[(t * 32 + ehu) * 4];
            creg = sigmoidf_(gf + ihv.y) * creg + sigmoidf_(gi + ihv.x) * tanhf(gg + ihv.z);
            const float hn = sigmoidf_(go + ihv.w) * tanhf(creg);
            __stcg(&g_h[((t + 1) & 1) * (Bn * Hn) + b * Hn + rank * 32 + ehu], hn);
        }
        __syncthreads();

        if (tid == 0)
            asm volatile("red.release.gpu.global.add.u32 [%0], %1;"
                         :: "l"(&g_cnt[b * Tn + t]), "r"(1u) : "memory");
        if (tid < 64) {
            unsigned v;
            do {
                asm volatile("ld.global.acquire.gpu.u32 %0,[%1];"
                             : "=r"(v) : "l"(&g_cnt[b * Tn + t]));
            } while (v < 8u);
            if (t < Tn - 1) {
                const float4 hvv = __ldcg((const float4*)
                    &g_h[((t + 1) & 1) * (Bn * Hn) + b * Hn + tid * 4]);
                *(float4*)&hsb[((t + 1) & 1) * 288 + (tid >> 3) * 36 + (tid & 7) * 4] = hvv;
            }
        }
        __syncthreads();
    }

    if (rank == 0 && tid < 32) {
        float p = 0.f;
        #pragma unroll
        for (int i = 0; i < 8; i++)
            p += __ldcg(&g_h[0 * (Bn * Hn) + b * Hn + i * 32 + tid])
                 * __ldg(&cls_W[i * 32 + tid]);
        #pragma unroll
        for (int o = 16; o; o >>= 1) p += __shfl_xor_sync(0xFFFFFFFFu, p, o);
        if (tid == 0) out[b] = p + cls_b[0];
    }
}

// =====================================================================
extern "C" void kernel_launch(void* const* d_in, const int* in_sizes, int n_in,
                              void* d_out, int out_size)
{
    (void)in_sizes; (void)n_in; (void)out_size;
    const float* x     = (const float*)d_in[0];
    const int*   ei    = (const int*)  d_in[1];
    const float* W1    = (const float*)d_in[2];
    const float* b1    = (const float*)d_in[3];
    const float* Wl    = (const float*)d_in[4];
    const float* Wr    = (const float*)d_in[5];
    const float* sb    = (const float*)d_in[6];
    const float* W2    = (const float*)d_in[7];
    const float* b2    = (const float*)d_in[8];
    const float* W_ih  = (const float*)d_in[9];
    const float* W_hh  = (const float*)d_in[10];
    const float* b_ih  = (const float*)d_in[11];
    const float* b_hh  = (const float*)d_in[12];
    const float* cls_W = (const float*)d_in[13];
    const float* cls_b = (const float*)d_in[14];
    float* out = (float*)d_out;

    const size_t smem1 = 55620 * sizeof(float);  // 222480 B
    cudaFuncSetAttribute(k_embed, cudaFuncAttributeMaxDynamicSharedMemorySize, (int)smem1);

    k_embed<<<NG, NT, smem1>>>(x, ei, W1, b1, Wl, Wr, sb, W2, b2);
    k_prep <<<64, 256>>>(W_ih, b_ih, b_hh);
    k_lstm <<<128, 512>>>(W_hh, cls_W, cls_b, out);
}